// round 14
// baseline (speedup 1.0000x reference)
#include <cuda_runtime.h>

// Problem sizes (fixed by the dataset)
#define BB 8
#define LL 2048
#define DD 128
#define CC 64              // chunks per batch
#define LC 32              // events per chunk (LL / CC)
#define EPSC 1e-6f

// Chunk z-sums T'[b,c,:] = sum_{j in c} m_j e_j exp(beta*(t_j - t_mid_b)),
// anchored at the batch midpoint time (exponents bounded by ~±12.5).
__device__ float    g_T[BB * CC * DD];     // 256 KB
// Per-batch monotone barrier tickets, padded to one 128B line each.
// Never reset: each launch adds 64 per batch; target = next multiple of 64.
__device__ unsigned g_cnt[BB * 32];

// ---------------------------------------------------------------------------
// Fused kernel: 256 threads / 8 warps per chunk, FLOAT4 lanes (same total
// instruction count as the 128-thr version, 2x warps/SM for stall overlap).
// Warp w owns events 4w..4w+3.
//
// Global-anchor factorization: exp(-beta(t_i-t_j)) = v_i * w_j with
//   w_j = m_j exp(beta(t_j-ta)), v_i = exp(-beta(t_i-ta)), ta = batch mid.
// lam_i = beta u_i v_i * ( e_i . (A_c + H_i) ),
//   A_c = unweighted prefix of T' over chunks < c,
//   H_i = in-chunk prefix of w_j e_j.
// ---------------------------------------------------------------------------
__global__ void __launch_bounds__(256) hawkes_fused(
    const int*   __restrict__ ids,
    const float* __restrict__ times,
    const float* __restrict__ mask,
    const float* __restrict__ emb,
    const float* __restrict__ u_table,
    const float* __restrict__ beta_p,
    float*       __restrict__ out)
{
    __shared__ float4 s_E4[LC * 32];       // 16 KB: 32 rows x 32 float4
    __shared__ float4 s_zsum[8 * 32];      // per-warp z partials (4 KB)
    __shared__ float4 s_carry[8 * 32];     // per-warp carry partials (4 KB)
    __shared__ float  s_pp[LC][33];        // padded per-lane dot partials
    __shared__ float  s_w[LC], s_v[LC], s_bu[LC];
    __shared__ float  s_r[LC];

    const int tid  = threadIdx.x;
    const int w    = tid >> 5;             // warp 0..7
    const int lane = tid & 31;
    const int g    = blockIdx.x;           // b*CC + c
    const int b    = g >> 6;
    const int c    = g & (CC - 1);
    const int base = b * LL + c * LC;

    // ---- E gather at instruction 0 (id broadcast -> coalesced LDG.128) ----
    const float4* embv = (const float4*)emb;
    float4 ebuf[4];
#pragma unroll
    for (int it = 0; it < 4; ++it) {
        int idx = it * 256 + tid;          // idx = row*32 + f4
        int row = idx >> 5, f4 = idx & 31;
        int id  = __ldg(&ids[base + row]);
        ebuf[it] = embv[(size_t)id * 32 + f4];
    }

    // ---- Overlapped precompute (batch-anchored factors) ----
    const float beta = beta_p[0];
    const float ta   = times[b * LL + LL / 2];   // same for all chunks of b

    if (c == 0 && tid == 0) out[b] = 0.f;  // released by the fence below

    if (tid < LC) {
        float t  = times[base + tid];
        float m  = mask[base + tid];
        int   id = ids[base + tid];
        s_w [tid] = m * __expf(beta * (t - ta));   // |exponent| <= ~12.5
        s_v [tid] = __expf(-beta * (t - ta));
        s_bu[tid] = beta * u_table[id];
    }

#pragma unroll
    for (int it = 0; it < 4; ++it) s_E4[it * 256 + tid] = ebuf[it];
    __syncthreads();

    // ---- Phase 1: per-warp z partials over 4 events each ----
    {
        float4 zz = {0.f, 0.f, 0.f, 0.f};
#pragma unroll
        for (int k = 0; k < 4; ++k) {
            int j = w * 4 + k;
            float wz = s_w[j];
            float4 e = s_E4[j * 32 + lane];
            zz.x += wz * e.x; zz.y += wz * e.y; zz.z += wz * e.z; zz.w += wz * e.w;
        }
        s_zsum[w * 32 + lane] = zz;
    }
    __syncthreads();
    if (tid < 32) {
        float4 T = {0.f, 0.f, 0.f, 0.f};
#pragma unroll
        for (int p = 0; p < 8; ++p) {
            float4 a = s_zsum[p * 32 + tid];
            T.x += a.x; T.y += a.y; T.z += a.z; T.w += a.w;
        }
        ((float4*)g_T)[g * 32 + tid] = T;
    }
    __syncthreads();
    __threadfence();                        // release g_T (and out[b]=0)
    unsigned target = 0;
    if (tid == 0) {
        unsigned t = atomicAdd(&g_cnt[b * 32], 1u);
        target = ((t >> 6) + 1u) << 6;      // next multiple of 64
    }

    // ---- Pre-barrier: in-chunk scan over 4 events (carry folded later) ----
    {
        float4 H = {0.f, 0.f, 0.f, 0.f};
#pragma unroll
        for (int p = 0; p < 7; ++p) {
            if (p < w) {                    // warp-uniform predicate
                float4 z = s_zsum[p * 32 + lane];
                H.x += z.x; H.y += z.y; H.z += z.z; H.w += z.w;
            }
        }
#pragma unroll
        for (int k = 0; k < 4; ++k) {
            int i = w * 4 + k;
            float4 e = s_E4[i * 32 + lane];
            s_pp[i][lane] = e.x * H.x + e.y * H.y + e.z * H.z + e.w * H.w;
            float wz = s_w[i];
            H.x += wz * e.x; H.y += wz * e.y; H.z += wz * e.z; H.w += wz * e.w;
        }
    }

    // ---- WAIT ----
    if (tid == 0) {
        unsigned cur;
        for (;;) {
            asm volatile("ld.global.acquire.gpu.u32 %0, [%1];"
                         : "=r"(cur) : "l"(&g_cnt[b * 32]));
            if (cur >= target) break;
            __nanosleep(64);
        }
    }
    __syncthreads();

    // ---- Carry: unweighted prefix of T', warp w covers 8 chunks ----
    const float4* Tb = (const float4*)g_T + (b * CC) * 32;
    {
        float4 A0 = {0,0,0,0}, A1 = {0,0,0,0};
        const int c2b = w * 8;
#pragma unroll
        for (int k = 0; k < 8; k += 2) {
            if (c2b + k     < c) { float4 T = Tb[(c2b + k    ) * 32 + lane];
                A0.x += T.x; A0.y += T.y; A0.z += T.z; A0.w += T.w; }
            if (c2b + k + 1 < c) { float4 T = Tb[(c2b + k + 1) * 32 + lane];
                A1.x += T.x; A1.y += T.y; A1.z += T.z; A1.w += T.w; }
        }
        float4 P;
        P.x = A0.x + A1.x; P.y = A0.y + A1.y;
        P.z = A0.z + A1.z; P.w = A0.w + A1.w;
        s_carry[w * 32 + lane] = P;
    }
    __syncthreads();

    // ---- Fold e_i . A into pp (A chunk-constant; sum 8 carry partials) ----
    {
        float4 A = {0.f, 0.f, 0.f, 0.f};
#pragma unroll
        for (int p = 0; p < 8; ++p) {
            float4 a = s_carry[p * 32 + lane];
            A.x += a.x; A.y += a.y; A.z += a.z; A.w += a.w;
        }
#pragma unroll
        for (int k = 0; k < 4; ++k) {
            int i = w * 4 + k;
            float4 e = s_E4[i * 32 + lane];
            s_pp[i][lane] += e.x * A.x + e.y * A.y + e.z * A.z + e.w * A.w;
        }
    }
    __syncthreads();

    // ---- 8 threads per event reduce its 32 lane-partials; parallel logs ----
    {
        int e = tid >> 3, q = tid & 7;
        float s = 0.f;
#pragma unroll
        for (int k = 0; k < 4; ++k) s += s_pp[e][q * 4 + k];   // conflict-free
        s += __shfl_xor_sync(0xffffffffu, s, 1);
        s += __shfl_xor_sync(0xffffffffu, s, 2);
        s += __shfl_xor_sync(0xffffffffu, s, 4);
        if (q == 0) {
            float lam = s_bu[e] * s_v[e] * s;
            s_r[e] = __logf(lam + EPSC);
        }
    }
    __syncthreads();

    if (tid < 32) {
        float lg = s_r[tid];
        lg += __shfl_xor_sync(0xffffffffu, lg, 16);
        lg += __shfl_xor_sync(0xffffffffu, lg, 8);
        lg += __shfl_xor_sync(0xffffffffu, lg, 4);
        lg += __shfl_xor_sync(0xffffffffu, lg, 2);
        lg += __shfl_xor_sync(0xffffffffu, lg, 1);
        if (tid == 0) atomicAdd(&out[b], lg);
    }
}

// ---------------------------------------------------------------------------
extern "C" void kernel_launch(void* const* d_in, const int* in_sizes, int n_in,
                              void* d_out, int out_size)
{
    const int*   ids   = (const int*)d_in[0];
    const float* times = (const float*)d_in[1];
    const float* mask  = (const float*)d_in[2];
    const float* emb   = (const float*)d_in[3];
    const float* u_tab = (const float*)d_in[4];
    const float* beta  = (const float*)d_in[5];
    float* out = (float*)d_out;

    hawkes_fused<<<BB * CC, 256>>>(ids, times, mask, emb, u_tab, beta, out);
}